// round 7
// baseline (speedup 1.0000x reference)
#include <cuda_runtime.h>
#include <cstdint>

#define VOCAB   128000
#define VOCAB4  32000
#define ROWS    256
#define CPR     19
#define CSZ     1684            // float4 per chunk; last chunk = 1688
#define NCTA    608             // = 152 SMs * 4 CTAs, one exact wave
#define K1NT    512
#define CAP     12288
#define SBUFCAP 2048
#define SUBCAP  512
#define K2NT    512
#define NEGV    (-1000000000.0f)
#define FULLMASK 0xffffffffu

// __device__ scratch (allocation-free rule compliant); zero-initialized at load.
__device__ unsigned long long g_cand[(size_t)ROWS * CAP];   // ~25 MB: (val<<32)|idx
__device__ int g_cnt[ROWS * 32];                            // 128B-strided counters

// ===================== K1: balanced stream-filter + per-chunk collect =====================
__global__ __launch_bounds__(K1NT, 4)
void k1_stream(const float* __restrict__ in, float* __restrict__ out) {
    __shared__ unsigned long long sbuf[SBUFCAP];   // 16 KB chunk-local candidates
    __shared__ float wtop[16];
    __shared__ float s_t0f;
    __shared__ int s_cnt, s_n, s_base;

    const int tid  = threadIdx.x;
    const int lane = tid & 31;
    const int wid  = tid >> 5;

    for (int w = 0; w < 8; w++) {
        const int c    = blockIdx.x + w * NCTA;
        const int row  = c / CPR;
        const int part = c % CPR;
        const float4* __restrict__ xc = (const float4*)(in  + (size_t)row * VOCAB) + part * CSZ;
        float4* __restrict__ yc       = (float4*)(out + (size_t)row * VOCAB) + part * CSZ;
        const int csz   = (part == CPR - 1) ? (VOCAB4 - (CPR - 1) * CSZ) : CSZ;  // 1688 / 1684
        const int gbase = part * CSZ * 4;

        // ---- per-chunk sampling: warp wid covers 64 consecutive float4 at wid*105 ----
        // (15*105+63 = 1638 < 1684, always in-bounds; these loads warm L2 for the stream pass)
        float4 sa = xc[wid * 105 + lane];
        float4 sb = xc[wid * 105 + 32 + lane];
        float sv[8] = {sa.x, sa.y, sa.z, sa.w, sb.x, sb.y, sb.z, sb.w};
        float wm = -3.4e38f;
#pragma unroll
        for (int r = 0; r < 4; r++) {           // extract warp top-4; wm ends as 4th max
            float lm = sv[0];
#pragma unroll
            for (int k = 1; k < 8; k++) lm = fmaxf(lm, sv[k]);
            wm = lm;
#pragma unroll
            for (int off = 16; off > 0; off >>= 1)
                wm = fmaxf(wm, __shfl_xor_sync(FULLMASK, wm, off));
            if (r < 3) {
                unsigned bal = __ballot_sync(FULLMASK, lm == wm);
                if (lane == __ffs(bal) - 1) {
                    bool done = false;
#pragma unroll
                    for (int k = 0; k < 8; k++)
                        if (!done && sv[k] == wm) { sv[k] = -3.4e38f; done = true; }
                }
            }
        }
        if (lane == 0) wtop[wid] = wm;
        __syncthreads();   // also closes previous chunk's flush before sbuf/s_cnt reuse
        if (tid == 0) {
            // t0 = min over 16 warps of warp-4th-max:
            //   each warp has >= 4 samples >= t0 -> >= 64 chunk elems >= t0
            //   -> row has >= 64 elems >= t0 -> t0 <= row's 50th-largest.
            // Hence the union of per-chunk candidate sets contains the row's top-50.
            float t0 = wtop[0];
            for (int q = 1; q < 16; q++) t0 = fminf(t0, wtop[q]);
            s_t0f = t0;
            s_cnt = 0;
        }
        __syncthreads();
        const float t0 = s_t0f;

        // ---- stream: filter + provisional store + collect ----
#pragma unroll
        for (int it = 0; it < 4; it++) {
            const int i = tid + it * K1NT;
            if (i < csz) {
                float4 v = xc[i];
                float4 o;
                o.x = (v.x >= t0) ? v.x : NEGV;
                o.y = (v.y >= t0) ? v.y : NEGV;
                o.z = (v.z >= t0) ? v.z : NEGV;
                o.w = (v.w >= t0) ? v.w : NEGV;
                __stcs(&yc[i], o);
                const int eb = gbase + 4 * i;
                if (v.x >= t0) { int p = atomicAdd(&s_cnt, 1); if (p < SBUFCAP) sbuf[p] = ((unsigned long long)__float_as_uint(v.x) << 32) | (unsigned)(eb);     }
                if (v.y >= t0) { int p = atomicAdd(&s_cnt, 1); if (p < SBUFCAP) sbuf[p] = ((unsigned long long)__float_as_uint(v.y) << 32) | (unsigned)(eb + 1); }
                if (v.z >= t0) { int p = atomicAdd(&s_cnt, 1); if (p < SBUFCAP) sbuf[p] = ((unsigned long long)__float_as_uint(v.z) << 32) | (unsigned)(eb + 2); }
                if (v.w >= t0) { int p = atomicAdd(&s_cnt, 1); if (p < SBUFCAP) sbuf[p] = ((unsigned long long)__float_as_uint(v.w) << 32) | (unsigned)(eb + 3); }
            }
        }
        __syncthreads();

        // ---- one bulk flush to global scratch ----
        if (tid == 0) {
            int n = s_cnt; if (n > SBUFCAP) n = SBUFCAP;
            s_n = n;
            s_base = atomicAdd(&g_cnt[row * 32], n);
        }
        __syncthreads();
        const int n = s_n, base = s_base;
        unsigned long long* __restrict__ dst = &g_cand[(size_t)row * CAP];
        for (int i = tid; i < n; i += K1NT) {
            int p = base + i;
            if (p < CAP) dst[p] = sbuf[i];
        }
        // next chunk's post-sample __syncthreads orders sbuf/s_cnt reuse
    }
}

// ===================== K2: per-row select + threshold + fixup + counter reset =====================
__global__ __launch_bounds__(K2NT, 2)
void k2_select(float* __restrict__ out) {
    __shared__ int   hist[1024];
    __shared__ float topbuf[SUBCAP];
    __shared__ float topsorted[50];
    __shared__ float e50[50];
    __shared__ float wmn[16], wmx[16];
    __shared__ float s_thresh;
    __shared__ int   s_scnt, s_b1;

    const int tid  = threadIdx.x;
    const int lane = tid & 31;
    const int wid  = tid >> 5;
    const int row  = blockIdx.x;
    const unsigned long long* __restrict__ cand = &g_cand[(size_t)row * CAP];
    float* __restrict__ y = out + (size_t)row * VOCAB;

    int cnt = g_cnt[row * 32];
    if (cnt > CAP) cnt = CAP;

    hist[tid] = 0; hist[tid + K2NT] = 0;
    if (tid == 0) { s_scnt = 0; s_b1 = 0; }
    if (tid < 50) topsorted[tid] = NEGV;

    // min/max over candidate values (range for the histogram)
    float mn = 3.4e38f, mx = -3.4e38f;
    for (int i = tid; i < cnt; i += K2NT) {
        float v = __uint_as_float((unsigned)(cand[i] >> 32));
        mn = fminf(mn, v); mx = fmaxf(mx, v);
    }
#pragma unroll
    for (int off = 16; off > 0; off >>= 1) {
        mn = fminf(mn, __shfl_xor_sync(FULLMASK, mn, off));
        mx = fmaxf(mx, __shfl_xor_sync(FULLMASK, mx, off));
    }
    if (lane == 0) { wmn[wid] = mn; wmx[wid] = mx; }
    __syncthreads();
    mn = wmn[0]; mx = wmx[0];
    for (int q = 1; q < 16; q++) { mn = fminf(mn, wmn[q]); mx = fmaxf(mx, wmx[q]); }
    const float scale = (mx > mn) ? (1023.0f / (mx - mn)) : 0.0f;

    // histogram (candidates are L2-hot)
    for (int i = tid; i < cnt; i += K2NT) {
        float v = __uint_as_float((unsigned)(cand[i] >> 32));
        int b = (int)((v - mn) * scale);
        b = b < 0 ? 0 : (b > 1023 ? 1023 : b);
        atomicAdd(&hist[b], 1);
    }
    __syncthreads();

    // B1 = largest bin with suffix count >= 50 (warp 0)
    if (wid == 0) {
        int c = 0;
        for (int j = 0; j < 32; j++) c += hist[lane * 32 + j];
        int s = c;
#pragma unroll
        for (int off = 1; off < 32; off <<= 1) {
            int t = __shfl_down_sync(FULLMASK, s, off);
            if (lane + off < 32) s += t;
        }
        unsigned bb = __ballot_sync(FULLMASK, (s >= 50) && (s - c < 50));
        if (bb) {
            int L = __ffs(bb) - 1;
            if (lane == L) {
                int acc = s - c;
                int B1 = L * 32;
                for (int j = 31; j >= 0; j--) {
                    acc += hist[L * 32 + j];
                    if (acc >= 50) { B1 = L * 32 + j; break; }
                }
                s_b1 = B1;
            }
        }
    }
    __syncthreads();
    const int B1 = s_b1;

    // sub-candidates (bin >= B1)
    for (int i = tid; i < cnt; i += K2NT) {
        float v = __uint_as_float((unsigned)(cand[i] >> 32));
        int b = (int)((v - mn) * scale);
        b = b < 0 ? 0 : (b > 1023 ? 1023 : b);
        if (b >= B1) { int p = atomicAdd(&s_scnt, 1); if (p < SUBCAP) topbuf[p] = v; }
    }
    __syncthreads();
    int sn = s_scnt; if (sn > SUBCAP) sn = SUBCAP;

    // rank-sort, keep top 50 descending
    for (int i = tid; i < sn; i += K2NT) {
        float vi = topbuf[i];
        int r = 0;
        for (int j = 0; j < sn; j++) {
            float vj = topbuf[j];
            r += (vj > vi) || (vj == vi && j < i);
        }
        if (r < 50) topsorted[r] = vi;
    }
    __syncthreads();

    // softmax over top-50 + nucleus cutoff (reference's shifted-cumsum rule)
    if (tid < 50) e50[tid] = expf(topsorted[tid] - topsorted[0]);
    __syncthreads();
    if (tid == 0) {
        float S = 0.0f;
        for (int i = 0; i < 50; i++) S += e50[i];
        float inv = 1.0f / S;
        float cum = e50[0] * inv;
        int m = 1;
        for (int i = 1; i < 50; i++) {
            if (cum <= 0.9f) m++;
            cum += e50[i] * inv;
        }
        s_thresh = topsorted[m - 1];
    }
    __syncthreads();

    // scatter fixup of provisionally-kept values below the final threshold
    const float t = s_thresh;
    for (int i = tid; i < cnt; i += K2NT) {
        unsigned long long cc = cand[i];
        float v = __uint_as_float((unsigned)(cc >> 32));
        if (v < t) y[(unsigned)(cc & 0xffffffffu)] = NEGV;
    }

    // reset counter for the next graph replay (deterministic restart state)
    if (tid == 0) g_cnt[row * 32] = 0;
}

extern "C" void kernel_launch(void* const* d_in, const int* in_sizes, int n_in,
                              void* d_out, int out_size) {
    const float* logits = (const float*)d_in[0];
    float* out = (float*)d_out;
    k1_stream<<<NCTA, K1NT>>>(logits, out);
    k2_select<<<ROWS, K2NT>>>(out);
}

// round 8
// speedup vs baseline: 1.0202x; 1.0202x over previous
#include <cuda_runtime.h>
#include <cstdint>

#define VOCAB 128000
#define VOCAB4 (VOCAB / 4)
#define NT 1024
#define NB (VOCAB / 8)        // 16000 bitmap bytes per row
#define NBW (NB / 4)          // 4000 bitmap words
#define CAP 6144
#define SUBCAP 512
#define NEGV (-1000000000.0f)
#define FULLMASK 0xffffffffu

// dyn smem: bitmap(16384) + buf(CAP*4) + bidx(CAP*4) + hist(4096)
#define DYN_SMEM (16384 + CAP * 8 + 4096)

__global__ __launch_bounds__(NT, 2)
void topk_topp_bitmap(const float* __restrict__ in, float* __restrict__ out) {
    extern __shared__ char dyn[];
    unsigned char* sbit = (unsigned char*)dyn;          // 16 KB bitmap
    float* buf  = (float*)(dyn + 16384);                // CAP values
    int*   bidx = (int*)(dyn + 16384 + CAP * 4);        // CAP indices
    int*   hist = (int*)(dyn + 16384 + CAP * 8);        // 1024 bins

    __shared__ float warp2nd[32];
    __shared__ float warpmax[32];
    __shared__ float topbuf[SUBCAP];
    __shared__ float topsorted[50];
    __shared__ float e50[50];
    __shared__ int   s_cnt, s_scnt, s_b1;
    __shared__ float s_t0, s_M, s_thresh;

    const int tid  = threadIdx.x;
    const int lane = tid & 31;
    const int wid  = tid >> 5;
    const float* __restrict__ x = in  + (size_t)blockIdx.x * VOCAB;
    float* __restrict__ y       = out + (size_t)blockIdx.x * VOCAB;

    // ---------- Phase 0: init ----------
    hist[tid] = 0;
    if (tid == 0) { s_cnt = 0; s_scnt = 0; s_b1 = 0; }
    if (tid < 50) topsorted[tid] = NEGV;

    // ---------- Phase 1: sample 8192 elems, per-warp top-2 ----------
    const float4* __restrict__ xs = (const float4*)(x + wid * 4000);
    float4 sa = xs[lane * 2];
    float4 sb = xs[lane * 2 + 1];
    float sv[8] = {sa.x, sa.y, sa.z, sa.w, sb.x, sb.y, sb.z, sb.w};

    float lm = sv[0];
#pragma unroll
    for (int k = 1; k < 8; k++) lm = fmaxf(lm, sv[k]);
    float wm = lm;
#pragma unroll
    for (int off = 16; off > 0; off >>= 1)
        wm = fmaxf(wm, __shfl_xor_sync(FULLMASK, wm, off));
    unsigned bal = __ballot_sync(FULLMASK, lm == wm);
    if (lane == (__ffs(bal) - 1)) {
        bool done = false;
#pragma unroll
        for (int k = 0; k < 8; k++)
            if (!done && sv[k] == wm) { sv[k] = -3.4e38f; done = true; }
    }
    float lm2 = sv[0];
#pragma unroll
    for (int k = 1; k < 8; k++) lm2 = fmaxf(lm2, sv[k]);
    float wm2 = lm2;
#pragma unroll
    for (int off = 16; off > 0; off >>= 1)
        wm2 = fmaxf(wm2, __shfl_xor_sync(FULLMASK, wm2, off));
    if (lane == 0) { warpmax[wid] = wm; warp2nd[wid] = wm2; }
    __syncthreads();

    if (tid == 0) {
        // t0 = 7th-smallest warp-2nd-max: 26 warps contribute >= 2 samples >= t0
        // -> >= 52 row elements >= t0 -> t0 <= row's 50th largest
        // -> the flagged set provably contains the row's top-50.
        float a[32];
        float M = warpmax[0];
        for (int w = 0; w < 32; w++) { a[w] = warp2nd[w]; M = fmaxf(M, warpmax[w]); }
        for (int k = 0; k < 7; k++) {
            int mi = k;
            for (int j = k + 1; j < 32; j++) if (a[j] < a[mi]) mi = j;
            float t = a[k]; a[k] = a[mi]; a[mi] = t;
        }
        s_t0 = a[6];
        s_M  = M;
    }
    __syncthreads();
    const float t0 = s_t0;
    const float M  = s_M;
    const float scale = (M > t0) ? (1023.0f / (M - t0)) : 0.0f;

    // ---------- Phase 2: BRANCHLESS streaming pass ----------
    // Thread handles byte b = two adjacent float4 (elements 8b..8b+7).
    // load 32B -> 8 selects -> store 32B -> pack 8 bits -> 1 smem byte store.
    const float4* __restrict__ x4 = (const float4*)x;
    float4* __restrict__ y4 = (float4*)y;
    for (int b = tid; b < NB; b += NT) {
        float4 va = x4[2 * b];
        float4 vb = x4[2 * b + 1];
        float4 wa, wb;
        wa.x = (va.x >= t0) ? va.x : NEGV;
        wa.y = (va.y >= t0) ? va.y : NEGV;
        wa.z = (va.z >= t0) ? va.z : NEGV;
        wa.w = (va.w >= t0) ? va.w : NEGV;
        wb.x = (vb.x >= t0) ? vb.x : NEGV;
        wb.y = (vb.y >= t0) ? vb.y : NEGV;
        wb.z = (vb.z >= t0) ? vb.z : NEGV;
        wb.w = (vb.w >= t0) ? vb.w : NEGV;
        __stcs(&y4[2 * b], wa);
        __stcs(&y4[2 * b + 1], wb);
        unsigned m = (unsigned)(va.x >= t0)
                   | ((unsigned)(va.y >= t0) << 1)
                   | ((unsigned)(va.z >= t0) << 2)
                   | ((unsigned)(va.w >= t0) << 3)
                   | ((unsigned)(vb.x >= t0) << 4)
                   | ((unsigned)(vb.y >= t0) << 5)
                   | ((unsigned)(vb.z >= t0) << 6)
                   | ((unsigned)(vb.w >= t0) << 7);
        sbit[b] = (unsigned char)m;
    }
    __syncthreads();

    // ---------- Phase 3: bitmap scan -> gather candidates + histogram ----------
    // word w bit p  ->  element e = 32*w + p   (little-endian byte order)
    const unsigned* __restrict__ sw32 = (const unsigned*)sbit;
    for (int w = tid; w < NBW; w += NT) {
        unsigned u = sw32[w];
        while (u) {
            int p = __ffs(u) - 1;
            u &= u - 1;
            int e = 32 * w + p;
            float v = x[e];                      // L2-warm gather (just streamed)
            int q = atomicAdd(&s_cnt, 1);
            if (q < CAP) {
                buf[q] = v;
                bidx[q] = e;
                int bin = (int)((v - t0) * scale);
                bin = bin < 0 ? 0 : (bin > 1023 ? 1023 : bin);
                atomicAdd(&hist[bin], 1);
            }
        }
    }
    __syncthreads();
    int cnt = s_cnt; if (cnt > CAP) cnt = CAP;

    // ---------- Phase 4: B1 = largest bin with suffix count >= 50 (warp 0) ----------
    if (wid == 0) {
        int c = 0;
        for (int j = 0; j < 32; j++) c += hist[lane * 32 + j];
        int s = c;
#pragma unroll
        for (int off = 1; off < 32; off <<= 1) {
            int t = __shfl_down_sync(FULLMASK, s, off);
            if (lane + off < 32) s += t;
        }
        unsigned bb = __ballot_sync(FULLMASK, (s >= 50) && (s - c < 50));
        if (bb) {
            int L = __ffs(bb) - 1;
            if (lane == L) {
                int acc = s - c;
                int B1 = L * 32;
                for (int j = 31; j >= 0; j--) {
                    acc += hist[L * 32 + j];
                    if (acc >= 50) { B1 = L * 32 + j; break; }
                }
                s_b1 = B1;
            }
        }
    }
    __syncthreads();
    const int B1 = s_b1;

    // ---------- Phase 5: sub-candidates (bin >= B1) ----------
    for (int i = tid; i < cnt; i += NT) {
        float v = buf[i];
        int bn = (int)((v - t0) * scale);
        bn = bn < 0 ? 0 : (bn > 1023 ? 1023 : bn);
        if (bn >= B1) { int p = atomicAdd(&s_scnt, 1); if (p < SUBCAP) topbuf[p] = v; }
    }
    __syncthreads();
    int sn = s_scnt; if (sn > SUBCAP) sn = SUBCAP;

    // ---------- Phase 6: rank-sort, keep top 50 descending ----------
    for (int i = tid; i < sn; i += NT) {
        float vi = topbuf[i];
        int r = 0;
        for (int j = 0; j < sn; j++) {
            float vj = topbuf[j];
            r += (vj > vi) || (vj == vi && j < i);
        }
        if (r < 50) topsorted[r] = vi;
    }
    __syncthreads();

    // ---------- Phase 7: softmax over top-50 + nucleus cutoff ----------
    if (tid < 50) e50[tid] = expf(topsorted[tid] - topsorted[0]);
    __syncthreads();
    if (tid == 0) {
        float S = 0.0f;
        for (int i = 0; i < 50; i++) S += e50[i];
        float inv = 1.0f / S;
        float cum = e50[0] * inv;
        int m = 1;
        for (int i = 1; i < 50; i++) {
            if (cum <= 0.9f) m++;
            cum += e50[i] * inv;
        }
        s_thresh = topsorted[m - 1];
    }
    __syncthreads();

    // ---------- Phase 8: scatter fixup of failed candidates ----------
    const float t = s_thresh;
    for (int i = tid; i < cnt; i += NT)
        if (buf[i] < t) y[bidx[i]] = NEGV;
}

extern "C" void kernel_launch(void* const* d_in, const int* in_sizes, int n_in,
                              void* d_out, int out_size) {
    const float* logits = (const float*)d_in[0];
    float* out = (float*)d_out;
    const int rows = out_size / VOCAB;  // 256
    cudaFuncSetAttribute(topk_topp_bitmap,
                         cudaFuncAttributeMaxDynamicSharedMemorySize, DYN_SMEM);
    topk_topp_bitmap<<<rows, NT, DYN_SMEM>>>(logits, out);
}

// round 9
// speedup vs baseline: 1.0462x; 1.0255x over previous
#include <cuda_runtime.h>
#include <cstdint>

#define VOCAB 128000
#define NT 1024
#define NB (VOCAB / 8)          // 16000 bitmap bytes per row
#define NBW_PAD 4096            // padded bitmap words (last 96 zeroed)
#define CAP 6144
#define SUBCAP 512
#define NEGV (-1000000000.0f)
#define FULLMASK 0xffffffffu

// dyn smem: bitmap(16KB) + eidx(24KB) + buf(24KB) + hist(4KB) = 68 KB
#define DYN_SMEM (NBW_PAD * 4 + CAP * 4 + CAP * 4 + 4096)

__global__ __launch_bounds__(NT, 2)
void topk_topp_v9(const float* __restrict__ in, float* __restrict__ out) {
    extern __shared__ char dyn[];
    unsigned* sw32 = (unsigned*)dyn;                         // 4096 bitmap words
    int*   eidx = (int*)(dyn + NBW_PAD * 4);                 // CAP element indices
    float* buf  = (float*)(dyn + NBW_PAD * 4 + CAP * 4);     // CAP values
    int*   hist = (int*)(dyn + NBW_PAD * 4 + CAP * 8);       // 1024 bins

    __shared__ float warp2nd[32];
    __shared__ float warpmax[32];
    __shared__ int   swcnt[32];      // per-warp candidate counts
    __shared__ int   swbase[32];     // per-warp exclusive bases
    __shared__ float topbuf[SUBCAP];
    __shared__ float topsorted[50];
    __shared__ float e50[50];
    __shared__ int   s_cnt, s_scnt, s_b1;
    __shared__ float s_t0, s_M, s_thresh;

    const int tid  = threadIdx.x;
    const int lane = tid & 31;
    const int wid  = tid >> 5;
    const float* __restrict__ x = in  + (size_t)blockIdx.x * VOCAB;
    float* __restrict__ y       = out + (size_t)blockIdx.x * VOCAB;

    // ---------- Phase 0: init (zero whole padded bitmap + hist) ----------
    hist[tid] = 0;
#pragma unroll
    for (int k = 0; k < 4; k++) sw32[tid + k * NT] = 0u;
    if (tid == 0) { s_scnt = 0; s_b1 = 0; }
    if (tid < 50) topsorted[tid] = NEGV;

    // ---------- Phase 1: sample 8192 elems, per-warp top-2 ----------
    const float4* __restrict__ xs = (const float4*)(x + wid * 4000);
    float4 sa = xs[lane * 2];
    float4 sb = xs[lane * 2 + 1];
    float sv[8] = {sa.x, sa.y, sa.z, sa.w, sb.x, sb.y, sb.z, sb.w};

    float lm = sv[0];
#pragma unroll
    for (int k = 1; k < 8; k++) lm = fmaxf(lm, sv[k]);
    float wm = lm;
#pragma unroll
    for (int off = 16; off > 0; off >>= 1)
        wm = fmaxf(wm, __shfl_xor_sync(FULLMASK, wm, off));
    unsigned bal = __ballot_sync(FULLMASK, lm == wm);
    if (lane == (__ffs(bal) - 1)) {
        bool done = false;
#pragma unroll
        for (int k = 0; k < 8; k++)
            if (!done && sv[k] == wm) { sv[k] = -3.4e38f; done = true; }
    }
    float lm2 = sv[0];
#pragma unroll
    for (int k = 1; k < 8; k++) lm2 = fmaxf(lm2, sv[k]);
    float wm2 = lm2;
#pragma unroll
    for (int off = 16; off > 0; off >>= 1)
        wm2 = fmaxf(wm2, __shfl_xor_sync(FULLMASK, wm2, off));
    if (lane == 0) { warpmax[wid] = wm; warp2nd[wid] = wm2; }
    __syncthreads();

    if (tid == 0) {
        // t0 = 7th-smallest warp-2nd-max: 26 warps contribute >= 2 samples >= t0
        // -> >= 52 row elements >= t0 -> t0 <= row's 50th largest
        // -> the flagged set provably contains the row's top-50.
        float a[32];
        float M = warpmax[0];
        for (int w = 0; w < 32; w++) { a[w] = warp2nd[w]; M = fmaxf(M, warpmax[w]); }
        for (int k = 0; k < 7; k++) {
            int mi = k;
            for (int j = k + 1; j < 32; j++) if (a[j] < a[mi]) mi = j;
            float t = a[k]; a[k] = a[mi]; a[mi] = t;
        }
        s_t0 = a[6];
        s_M  = M;
    }
    __syncthreads();
    const float t0 = s_t0;
    const float M  = s_M;
    const float scale = (M > t0) ? (1023.0f / (M - t0)) : 0.0f;

    // ---------- Phase 2: BRANCHLESS streaming pass ----------
    // thread handles bitmap byte b = elements 8b..8b+7 (2 adjacent float4)
    const float4* __restrict__ x4 = (const float4*)x;
    float4* __restrict__ y4 = (float4*)y;
    unsigned char* sbit = (unsigned char*)sw32;
    for (int b = tid; b < NB; b += NT) {
        float4 va = x4[2 * b];
        float4 vb = x4[2 * b + 1];
        float4 wa, wb;
        wa.x = (va.x >= t0) ? va.x : NEGV;
        wa.y = (va.y >= t0) ? va.y : NEGV;
        wa.z = (va.z >= t0) ? va.z : NEGV;
        wa.w = (va.w >= t0) ? va.w : NEGV;
        wb.x = (vb.x >= t0) ? vb.x : NEGV;
        wb.y = (vb.y >= t0) ? vb.y : NEGV;
        wb.z = (vb.z >= t0) ? vb.z : NEGV;
        wb.w = (vb.w >= t0) ? vb.w : NEGV;
        __stcs(&y4[2 * b], wa);
        __stcs(&y4[2 * b + 1], wb);
        unsigned m = (unsigned)(va.x >= t0)
                   | ((unsigned)(va.y >= t0) << 1)
                   | ((unsigned)(va.z >= t0) << 2)
                   | ((unsigned)(va.w >= t0) << 3)
                   | ((unsigned)(vb.x >= t0) << 4)
                   | ((unsigned)(vb.y >= t0) << 5)
                   | ((unsigned)(vb.z >= t0) << 6)
                   | ((unsigned)(vb.w >= t0) << 7);
        sbit[b] = (unsigned char)m;
    }
    __syncthreads();

    // ---------- Phase 3a: popc + block scan -> ordered index compaction ----------
    // thread owns 4 consecutive words [tid*4, tid*4+4)
    unsigned w0 = sw32[tid * 4], w1 = sw32[tid * 4 + 1];
    unsigned w2 = sw32[tid * 4 + 2], w3 = sw32[tid * 4 + 3];
    int pc = __popc(w0) + __popc(w1) + __popc(w2) + __popc(w3);
    // warp exclusive scan
    int excl = pc;
#pragma unroll
    for (int off = 1; off < 32; off <<= 1) {
        int t = __shfl_up_sync(FULLMASK, excl, off);
        if (lane >= off) excl += t;
    }
    excl -= pc;                                  // exclusive within warp
    if (lane == 31) swcnt[wid] = excl + pc;      // warp total
    __syncthreads();
    if (wid == 0) {
        int v = swcnt[lane];
        int e = v;
#pragma unroll
        for (int off = 1; off < 32; off <<= 1) {
            int t = __shfl_up_sync(FULLMASK, e, off);
            if (lane >= off) e += t;
        }
        swbase[lane] = e - v;                    // exclusive base per warp
        if (lane == 31) s_cnt = e;               // block total
    }
    __syncthreads();
    int off0 = swbase[wid] + excl;
    const int ebase = tid * 128;                 // element base of word tid*4
#define DRAIN(W, EB)                                                      \
    { unsigned u = (W); int eb = (EB);                                    \
      while (u) { int p = __ffs(u) - 1; u &= u - 1;                       \
                  if (off0 < CAP) eidx[off0] = eb + p; off0++; } }
    DRAIN(w0, ebase)
    DRAIN(w1, ebase + 32)
    DRAIN(w2, ebase + 64)
    DRAIN(w3, ebase + 96)
#undef DRAIN
    __syncthreads();
    int cnt = s_cnt; if (cnt > CAP) cnt = CAP;

    // ---------- Phase 3b: dense parallel gather + histogram ----------
    for (int i = tid; i < cnt; i += NT) {
        float v = x[eidx[i]];                    // all gathers in flight together
        buf[i] = v;
        int bn = (int)((v - t0) * scale);
        bn = bn < 0 ? 0 : (bn > 1023 ? 1023 : bn);
        atomicAdd(&hist[bn], 1);
    }
    __syncthreads();

    // ---------- Phase 4: B1 = largest bin with suffix count >= 50 (warp 0) ----------
    if (wid == 0) {
        int c = 0;
        for (int j = 0; j < 32; j++) c += hist[lane * 32 + j];
        int s = c;
#pragma unroll
        for (int off = 1; off < 32; off <<= 1) {
            int t = __shfl_down_sync(FULLMASK, s, off);
            if (lane + off < 32) s += t;
        }
        unsigned bb = __ballot_sync(FULLMASK, (s >= 50) && (s - c < 50));
        if (bb) {
            int L = __ffs(bb) - 1;
            if (lane == L) {
                int acc = s - c;
                int B1 = L * 32;
                for (int j = 31; j >= 0; j--) {
                    acc += hist[L * 32 + j];
                    if (acc >= 50) { B1 = L * 32 + j; break; }
                }
                s_b1 = B1;
            }
        }
    }
    __syncthreads();
    const int B1 = s_b1;

    // ---------- Phase 5: sub-candidates (bin >= B1) ----------
    for (int i = tid; i < cnt; i += NT) {
        float v = buf[i];
        int bn = (int)((v - t0) * scale);
        bn = bn < 0 ? 0 : (bn > 1023 ? 1023 : bn);
        if (bn >= B1) { int p = atomicAdd(&s_scnt, 1); if (p < SUBCAP) topbuf[p] = v; }
    }
    __syncthreads();
    int sn = s_scnt; if (sn > SUBCAP) sn = SUBCAP;

    // ---------- Phase 6: rank-sort, keep top 50 descending ----------
    for (int i = tid; i < sn; i += NT) {
        float vi = topbuf[i];
        int r = 0;
        for (int j = 0; j < sn; j++) {
            float vj = topbuf[j];
            r += (vj > vi) || (vj == vi && j < i);
        }
        if (r < 50) topsorted[r] = vi;
    }
    __syncthreads();

    // ---------- Phase 7: softmax over top-50 + nucleus cutoff ----------
    if (tid < 50) e50[tid] = expf(topsorted[tid] - topsorted[0]);
    __syncthreads();
    if (tid == 0) {
        float S = 0.0f;
        for (int i = 0; i < 50; i++) S += e50[i];
        float inv = 1.0f / S;
        float cum = e50[0] * inv;
        int m = 1;
        for (int i = 1; i < 50; i++) {
            if (cum <= 0.9f) m++;
            cum += e50[i] * inv;
        }
        s_thresh = topsorted[m - 1];
    }
    __syncthreads();

    // ---------- Phase 8: scatter fixup of failed candidates ----------
    const float t = s_thresh;
    for (int i = tid; i < cnt; i += NT)
        if (buf[i] < t) y[eidx[i]] = NEGV;
}

extern "C" void kernel_launch(void* const* d_in, const int* in_sizes, int n_in,
                              void* d_out, int out_size) {
    const float* logits = (const float*)d_in[0];
    float* out = (float*)d_out;
    const int rows = out_size / VOCAB;  // 256
    cudaFuncSetAttribute(topk_topp_v9,
                         cudaFuncAttributeMaxDynamicSharedMemorySize, DYN_SMEM);
    topk_topp_v9<<<rows, NT, DYN_SMEM>>>(logits, out);
}

// round 11
// speedup vs baseline: 1.3011x; 1.2437x over previous
#include <cuda_runtime.h>

#define VOCAB 128000
#define VOCAB4 (VOCAB / 4)
#define NT 1024
#define NFULL 31                  // 31*1024 = 31744 full iterations
#define NREM (VOCAB4 - NFULL * NT)  // 256 remainder lanes
#define CAP 6144
#define SUBCAP 512
#define NEGV (-1000000000.0f)
#define FULLMASK 0xffffffffu

#define DYN_SMEM (CAP * 8 + 1024 * 4)   // buf + bidx + hist = 53248 bytes

__global__ __launch_bounds__(NT, 2)
void topk_topp_v10(const float* __restrict__ in, float* __restrict__ out) {
    extern __shared__ char dyn[];
    float* buf  = (float*)dyn;                  // CAP candidate values
    int*   bidx = (int*)(dyn + CAP * 4);        // CAP candidate indices
    int*   hist = (int*)(dyn + CAP * 8);        // 1024 bins

    __shared__ float warp2nd[32];
    __shared__ float warpmax[32];
    __shared__ float topbuf[SUBCAP];
    __shared__ float topsorted[50];
    __shared__ float e50[50];
    __shared__ int   s_cnt, s_scnt, s_b1;
    __shared__ float s_t0, s_M, s_thresh;

    const int tid  = threadIdx.x;
    const int lane = tid & 31;
    const int wid  = tid >> 5;
    const float* __restrict__ x = in  + (size_t)blockIdx.x * VOCAB;
    float* __restrict__ y       = out + (size_t)blockIdx.x * VOCAB;

    // ---------- Phase 0: init ----------
    hist[tid] = 0;
    if (tid == 0) { s_cnt = 0; s_scnt = 0; s_b1 = 0; }
    if (tid < 50) topsorted[tid] = NEGV;

    // ---------- Phase 1: sample 8192 elems, per-warp top-2 ----------
    const float4* __restrict__ xs = (const float4*)(x + wid * 4000);
    float4 sa = xs[lane * 2];
    float4 sb = xs[lane * 2 + 1];
    float sv[8] = {sa.x, sa.y, sa.z, sa.w, sb.x, sb.y, sb.z, sb.w};

    float lm = sv[0];
#pragma unroll
    for (int k = 1; k < 8; k++) lm = fmaxf(lm, sv[k]);
    float wm = lm;
#pragma unroll
    for (int off = 16; off > 0; off >>= 1)
        wm = fmaxf(wm, __shfl_xor_sync(FULLMASK, wm, off));
    unsigned bal = __ballot_sync(FULLMASK, lm == wm);
    if (lane == (__ffs(bal) - 1)) {
        bool done = false;
#pragma unroll
        for (int k = 0; k < 8; k++)
            if (!done && sv[k] == wm) { sv[k] = -3.4e38f; done = true; }
    }
    float lm2 = sv[0];
#pragma unroll
    for (int k = 1; k < 8; k++) lm2 = fmaxf(lm2, sv[k]);
    float wm2 = lm2;
#pragma unroll
    for (int off = 16; off > 0; off >>= 1)
        wm2 = fmaxf(wm2, __shfl_xor_sync(FULLMASK, wm2, off));
    if (lane == 0) { warpmax[wid] = wm; warp2nd[wid] = wm2; }
    __syncthreads();

    if (tid == 0) {
        // t0 = 7th-smallest warp-2nd-max: 26 warps contribute >= 2 samples >= t0
        // -> >= 52 row elements >= t0 -> t0 <= row's 50th largest
        // -> candidate set provably contains the top-50.
        float a[32];
        float M = warpmax[0];
        for (int w = 0; w < 32; w++) { a[w] = warp2nd[w]; M = fmaxf(M, warpmax[w]); }
        for (int k = 0; k < 7; k++) {
            int mi = k;
            for (int j = k + 1; j < 32; j++) if (a[j] < a[mi]) mi = j;
            float t = a[k]; a[k] = a[mi]; a[mi] = t;
        }
        s_t0 = a[6];
        s_M  = M;
    }
    __syncthreads();
    const float t0 = s_t0;
    const float M  = s_M;
    const float scale = (M > t0) ? (1023.0f / (M - t0)) : 0.0f;

    // ---------- Phase 2: fused streaming pass (compile-time trip, ldcs/stcs) ----------
    const float4* __restrict__ x4 = (const float4*)x;
    float4* __restrict__ y4 = (float4*)y;

#define BODY(IDX)                                                                     \
    {                                                                                 \
        const int _i = (IDX);                                                         \
        float4 v = __ldcs(&x4[_i]);                                                   \
        float4 w;                                                                     \
        w.x = (v.x >= t0) ? v.x : NEGV;                                               \
        w.y = (v.y >= t0) ? v.y : NEGV;                                               \
        w.z = (v.z >= t0) ? v.z : NEGV;                                               \
        w.w = (v.w >= t0) ? v.w : NEGV;                                               \
        __stcs(&y4[_i], w);                                                           \
        if (v.x >= t0) { int p = atomicAdd(&s_cnt, 1); if (p < CAP) { buf[p] = v.x;   \
            bidx[p] = 4 * _i;     int b = (int)((v.x - t0) * scale);                  \
            b = b < 0 ? 0 : (b > 1023 ? 1023 : b); atomicAdd(&hist[b], 1); } }        \
        if (v.y >= t0) { int p = atomicAdd(&s_cnt, 1); if (p < CAP) { buf[p] = v.y;   \
            bidx[p] = 4 * _i + 1; int b = (int)((v.y - t0) * scale);                  \
            b = b < 0 ? 0 : (b > 1023 ? 1023 : b); atomicAdd(&hist[b], 1); } }        \
        if (v.z >= t0) { int p = atomicAdd(&s_cnt, 1); if (p < CAP) { buf[p] = v.z;   \
            bidx[p] = 4 * _i + 2; int b = (int)((v.z - t0) * scale);                  \
            b = b < 0 ? 0 : (b > 1023 ? 1023 : b); atomicAdd(&hist[b], 1); } }        \
        if (v.w >= t0) { int p = atomicAdd(&s_cnt, 1); if (p < CAP) { buf[p] = v.w;   \
            bidx[p] = 4 * _i + 3; int b = (int)((v.w - t0) * scale);                  \
            b = b < 0 ? 0 : (b > 1023 ? 1023 : b); atomicAdd(&hist[b], 1); } }        \
    }

#pragma unroll 2
    for (int it = 0; it < NFULL; it++)
        BODY(tid + it * NT)
    if (tid < NREM)
        BODY(tid + NFULL * NT)
#undef BODY

    __syncthreads();
    int cnt = s_cnt; if (cnt > CAP) cnt = CAP;

    // ---------- Phase 4: B1 = largest bin with suffix count >= 50 (warp 0) ----------
    if (wid == 0) {
        int c = 0;
        for (int j = 0; j < 32; j++) c += hist[lane * 32 + j];
        int s = c;
#pragma unroll
        for (int off = 1; off < 32; off <<= 1) {
            int t = __shfl_down_sync(FULLMASK, s, off);
            if (lane + off < 32) s += t;
        }
        unsigned bb = __ballot_sync(FULLMASK, (s >= 50) && (s - c < 50));
        if (bb) {
            int L = __ffs(bb) - 1;
            if (lane == L) {
                int acc = s - c;
                int B1 = L * 32;
                for (int j = 31; j >= 0; j--) {
                    acc += hist[L * 32 + j];
                    if (acc >= 50) { B1 = L * 32 + j; break; }
                }
                s_b1 = B1;
            }
        }
    }
    __syncthreads();
    const int B1 = s_b1;

    // ---------- Phase 5: sub-candidates (bin >= B1) ----------
    for (int i = tid; i < cnt; i += NT) {
        float v = buf[i];
        int b = (int)((v - t0) * scale);
        b = b < 0 ? 0 : (b > 1023 ? 1023 : b);
        if (b >= B1) { int p = atomicAdd(&s_scnt, 1); if (p < SUBCAP) topbuf[p] = v; }
    }
    __syncthreads();
    int sn = s_scnt; if (sn > SUBCAP) sn = SUBCAP;

    // ---------- Phase 6: rank-sort, keep top 50 descending ----------
    for (int i = tid; i < sn; i += NT) {
        float vi = topbuf[i];
        int r = 0;
        for (int j = 0; j < sn; j++) {
            float vj = topbuf[j];
            r += (vj > vi) || (vj == vi && j < i);
        }
        if (r < 50) topsorted[r] = vi;
    }
    __syncthreads();

    // ---------- Phase 7: softmax over top-50 (parallel exp) + nucleus cutoff ----------
    if (tid < 50) e50[tid] = expf(topsorted[tid] - topsorted[0]);
    __syncthreads();
    if (tid == 0) {
        float S = 0.0f;
        for (int i = 0; i < 50; i++) S += e50[i];
        float inv = 1.0f / S;
        float cum = e50[0] * inv;
        int m = 1;
        for (int i = 1; i < 50; i++) {
            if (cum <= 0.9f) m++;
            cum += e50[i] * inv;
        }
        s_thresh = topsorted[m - 1];
    }
    __syncthreads();

    // ---------- Phase 8: scatter fixup of failed candidates ----------
    const float t = s_thresh;
    for (int i = tid; i < cnt; i += NT)
        if (buf[i] < t) y[bidx[i]] = NEGV;
}

extern "C" void kernel_launch(void* const* d_in, const int* in_sizes, int n_in,
                              void* d_out, int out_size) {
    const float* logits = (const float*)d_in[0];
    float* out = (float*)d_out;
    const int rows = out_size / VOCAB;  // 256
    cudaFuncSetAttribute(topk_topp_v10,
                         cudaFuncAttributeMaxDynamicSharedMemorySize, DYN_SMEM);
    topk_topp_v10<<<rows, NT, DYN_SMEM>>>(logits, out);
}

// round 14
// speedup vs baseline: 1.3142x; 1.0100x over previous
#include <cuda_runtime.h>

#define VOCAB 128000
#define VOCAB4 (VOCAB / 4)
#define NT 1024
#define NFULL 31                    // 31*1024 = 31744 full iterations
#define NREM (VOCAB4 - NFULL * NT)  // 256 remainder lanes
#define PFD (4 * NT)                // prefetch distance: 4 block-iterations = 64 KB
#define CAP 6144
#define SUBCAP 512
#define NEGV (-1000000000.0f)
#define FULLMASK 0xffffffffu

#define DYN_SMEM (CAP * 8 + 1024 * 4)   // buf + bidx + hist = 53248 bytes

__global__ __launch_bounds__(NT, 2)
void topk_topp_v12(const float* __restrict__ in, float* __restrict__ out) {
    extern __shared__ char dyn[];
    float* buf  = (float*)dyn;                  // CAP candidate values
    int*   bidx = (int*)(dyn + CAP * 4);        // CAP candidate indices
    int*   hist = (int*)(dyn + CAP * 8);        // 1024 bins

    __shared__ float warp2nd[32];
    __shared__ float warpmax[32];
    __shared__ float topbuf[SUBCAP];
    __shared__ float topsorted[50];
    __shared__ float e50[50];
    __shared__ int   s_cnt, s_scnt, s_b1;
    __shared__ float s_t0, s_M, s_thresh;

    const int tid  = threadIdx.x;
    const int lane = tid & 31;
    const int wid  = tid >> 5;
    const float* __restrict__ x = in  + (size_t)blockIdx.x * VOCAB;
    float* __restrict__ y       = out + (size_t)blockIdx.x * VOCAB;

    // ---------- Phase 0: init ----------
    hist[tid] = 0;
    if (tid == 0) { s_cnt = 0; s_scnt = 0; s_b1 = 0; }
    if (tid < 50) topsorted[tid] = NEGV;

    // ---------- Phase 1: sample 8192 elems, per-warp top-2 ----------
    const float4* __restrict__ xs = (const float4*)(x + wid * 4000);
    float4 sa = xs[lane * 2];
    float4 sb = xs[lane * 2 + 1];
    float sv[8] = {sa.x, sa.y, sa.z, sa.w, sb.x, sb.y, sb.z, sb.w};

    float lm = sv[0];
#pragma unroll
    for (int k = 1; k < 8; k++) lm = fmaxf(lm, sv[k]);
    float wm = lm;
#pragma unroll
    for (int off = 16; off > 0; off >>= 1)
        wm = fmaxf(wm, __shfl_xor_sync(FULLMASK, wm, off));
    unsigned bal = __ballot_sync(FULLMASK, lm == wm);
    if (lane == (__ffs(bal) - 1)) {
        bool done = false;
#pragma unroll
        for (int k = 0; k < 8; k++)
            if (!done && sv[k] == wm) { sv[k] = -3.4e38f; done = true; }
    }
    float lm2 = sv[0];
#pragma unroll
    for (int k = 1; k < 8; k++) lm2 = fmaxf(lm2, sv[k]);
    float wm2 = lm2;
#pragma unroll
    for (int off = 16; off > 0; off >>= 1)
        wm2 = fmaxf(wm2, __shfl_xor_sync(FULLMASK, wm2, off));
    if (lane == 0) { warpmax[wid] = wm; warp2nd[wid] = wm2; }
    __syncthreads();

    if (tid == 0) {
        // t0 = 7th-smallest warp-2nd-max: 26 warps contribute >= 2 samples >= t0
        // -> >= 52 row elements >= t0 -> t0 <= row's 50th largest
        // -> candidate set provably contains the top-50.
        float a[32];
        float M = warpmax[0];
        for (int w = 0; w < 32; w++) { a[w] = warp2nd[w]; M = fmaxf(M, warpmax[w]); }
        for (int k = 0; k < 7; k++) {
            int mi = k;
            for (int j = k + 1; j < 32; j++) if (a[j] < a[mi]) mi = j;
            float t = a[k]; a[k] = a[mi]; a[mi] = t;
        }
        s_t0 = a[6];
        s_M  = M;
    }
    __syncthreads();
    const float t0 = s_t0;
    const float M  = s_M;
    const float scale = (M > t0) ? (1023.0f / (M - t0)) : 0.0f;

    // ---------- Phase 2: fused streaming pass + L2 prefetch ----------
    const float4* __restrict__ x4 = (const float4*)x;
    float4* __restrict__ y4 = (float4*)y;
    const bool pfer = ((tid & 7) == 0);       // 1 thread per 128B line prefetches

#define BODY(IDX)                                                                     \
    {                                                                                 \
        const int _i = (IDX);                                                         \
        if (pfer) {                                                                   \
            int _pf = _i + PFD;                                                       \
            _pf = (_pf < VOCAB4) ? _pf : (VOCAB4 - 8);                                \
            asm volatile("prefetch.global.L2 [%0];" :: "l"(x4 + _pf));                \
        }                                                                             \
        float4 v = __ldcs(&x4[_i]);                                                   \
        float4 w;                                                                     \
        w.x = (v.x >= t0) ? v.x : NEGV;                                               \
        w.y = (v.y >= t0) ? v.y : NEGV;                                               \
        w.z = (v.z >= t0) ? v.z : NEGV;                                               \
        w.w = (v.w >= t0) ? v.w : NEGV;                                               \
        __stcs(&y4[_i], w);                                                           \
        if (v.x >= t0) { int p = atomicAdd(&s_cnt, 1); if (p < CAP) { buf[p] = v.x;   \
            bidx[p] = 4 * _i;     int b = (int)((v.x - t0) * scale);                  \
            b = b < 0 ? 0 : (b > 1023 ? 1023 : b); atomicAdd(&hist[b], 1); } }        \
        if (v.y >= t0) { int p = atomicAdd(&s_cnt, 1); if (p < CAP) { buf[p] = v.y;   \
            bidx[p] = 4 * _i + 1; int b = (int)((v.y - t0) * scale);                  \
            b = b < 0 ? 0 : (b > 1023 ? 1023 : b); atomicAdd(&hist[b], 1); } }        \
        if (v.z >= t0) { int p = atomicAdd(&s_cnt, 1); if (p < CAP) { buf[p] = v.z;   \
            bidx[p] = 4 * _i + 2; int b = (int)((v.z - t0) * scale);                  \
            b = b < 0 ? 0 : (b > 1023 ? 1023 : b); atomicAdd(&hist[b], 1); } }        \
        if (v.w >= t0) { int p = atomicAdd(&s_cnt, 1); if (p < CAP) { buf[p] = v.w;   \
            bidx[p] = 4 * _i + 3; int b = (int)((v.w - t0) * scale);                  \
            b = b < 0 ? 0 : (b > 1023 ? 1023 : b); atomicAdd(&hist[b], 1); } }        \
    }

#pragma unroll 2
    for (int it = 0; it < NFULL; it++)
        BODY(tid + it * NT)
    if (tid < NREM)
        BODY(tid + NFULL * NT)
#undef BODY

    __syncthreads();
    int cnt = s_cnt; if (cnt > CAP) cnt = CAP;

    // ---------- Phase 4: B1 = largest bin with suffix count >= 50 (warp 0) ----------
    if (wid == 0) {
        int c = 0;
        for (int j = 0; j < 32; j++) c += hist[lane * 32 + j];
        int s = c;
#pragma unroll
        for (int off = 1; off < 32; off <<= 1) {
            int t = __shfl_down_sync(FULLMASK, s, off);
            if (lane + off < 32) s += t;
        }
        unsigned bb = __ballot_sync(FULLMASK, (s >= 50) && (s - c < 50));
        if (bb) {
            int L = __ffs(bb) - 1;
            if (lane == L) {
                int acc = s - c;
                int B1 = L * 32;
                for (int j = 31; j >= 0; j--) {
                    acc += hist[L * 32 + j];
                    if (acc >= 50) { B1 = L * 32 + j; break; }
                }
                s_b1 = B1;
            }
        }
    }
    __syncthreads();
    const int B1 = s_b1;

    // ---------- Phase 5: sub-candidates (bin >= B1) ----------
    for (int i = tid; i < cnt; i += NT) {
        float v = buf[i];
        int b = (int)((v - t0) * scale);
        b = b < 0 ? 0 : (b > 1023 ? 1023 : b);
        if (b >= B1) { int p = atomicAdd(&s_scnt, 1); if (p < SUBCAP) topbuf[p] = v; }
    }
    __syncthreads();
    int sn = s_scnt; if (sn > SUBCAP) sn = SUBCAP;

    // ---------- Phase 6: rank-sort, keep top 50 descending ----------
    for (int i = tid; i < sn; i += NT) {
        float vi = topbuf[i];
        int r = 0;
        for (int j = 0; j < sn; j++) {
            float vj = topbuf[j];
            r += (vj > vi) || (vj == vi && j < i);
        }
        if (r < 50) topsorted[r] = vi;
    }
    __syncthreads();

    // ---------- Phase 7: softmax over top-50 (parallel exp) + nucleus cutoff ----------
    if (tid < 50) e50[tid] = expf(topsorted[tid] - topsorted[0]);
    __syncthreads();
    if (tid == 0) {
        float S = 0.0f;
        for (int i = 0; i < 50; i++) S += e50[i];
        float inv = 1.0f / S;
        float cum = e50[0] * inv;
        int m = 1;
        for (int i = 1; i < 50; i++) {
            if (cum <= 0.9f) m++;
            cum += e50[i] * inv;
        }
        s_thresh = topsorted[m - 1];
    }
    __syncthreads();

    // ---------- Phase 8: scatter fixup of failed candidates ----------
    const float t = s_thresh;
    for (int i = tid; i < cnt; i += NT)
        if (buf[i] < t) y[bidx[i]] = NEGV;
}

extern "C" void kernel_launch(void* const* d_in, const int* in_sizes, int n_in,
                              void* d_out, int out_size) {
    const float* logits = (const float*)d_in[0];
    float* out = (float*)d_out;
    const int rows = out_size / VOCAB;  // 256
    cudaFuncSetAttribute(topk_topp_v12,
                         cudaFuncAttributeMaxDynamicSharedMemorySize, DYN_SMEM);
    topk_topp_v12<<<rows, NT, DYN_SMEM>>>(logits, out);
}